// round 1
// baseline (speedup 1.0000x reference)
#include <cuda_runtime.h>
#include <cuda_bf16.h>

// Problem shape (from setup_inputs): hidden_vectors (1024, 512) f32, labels (1024,) i32.
// Scratch in __device__ globals (no allocations allowed).
#define N_MAX 1024
#define D_MAX 512

__device__ float g_h[N_MAX * D_MAX];        // normalized rows
__device__ float g_sim[N_MAX * N_MAX];      // cosine similarity matrix
__device__ float g_rowloss[N_MAX];
__device__ float g_rowcnt[N_MAX];

// ---------------------------------------------------------------------------
// K1: L2-normalize rows. One warp per row. blockDim = (32, 8).
// ---------------------------------------------------------------------------
__global__ void knorm(const float* __restrict__ x, int n, int d) {
    int row = blockIdx.x * blockDim.y + threadIdx.y;
    if (row >= n) return;
    const float4* xr = (const float4*)(x + (size_t)row * d);
    int nv = d >> 2;
    float s = 0.f;
    for (int i = threadIdx.x; i < nv; i += 32) {
        float4 v = xr[i];
        s += v.x * v.x + v.y * v.y + v.z * v.z + v.w * v.w;
    }
#pragma unroll
    for (int o = 16; o; o >>= 1) s += __shfl_xor_sync(0xffffffffu, s, o);
    float inv = rsqrtf(s);
    float4* hr = (float4*)(g_h + (size_t)row * d);
    for (int i = threadIdx.x; i < nv; i += 32) {
        float4 v = xr[i];
        v.x *= inv; v.y *= inv; v.z *= inv; v.w *= inv;
        hr[i] = v;
    }
}

// ---------------------------------------------------------------------------
// K2: sim = h @ h^T, fp32 tiled GEMM. 64x64 tile, BK=16, 256 threads,
// 4x4 register tile per thread, float4 smem loads in the inner product.
// ---------------------------------------------------------------------------
__global__ void kgemm(int n, int d) {
    __shared__ float As[16][64];
    __shared__ float Bs[16][64];
    const int bi = blockIdx.y * 64;
    const int bj = blockIdx.x * 64;
    const int tid = threadIdx.x;          // 0..255
    const int tx = tid & 15;
    const int ty = tid >> 4;
    const int lr = tid >> 2;              // 0..63 (tile row for loading)
    const int lk = (tid & 3) << 2;        // 0,4,8,12 (k group for loading)

    float acc[4][4];
#pragma unroll
    for (int r = 0; r < 4; r++)
#pragma unroll
        for (int c = 0; c < 4; c++) acc[r][c] = 0.f;

    const float* Arow = g_h + (size_t)(bi + lr) * d + lk;
    const float* Brow = g_h + (size_t)(bj + lr) * d + lk;

    for (int k0 = 0; k0 < d; k0 += 16) {
        float4 av = *(const float4*)(Arow + k0);
        float4 bv = *(const float4*)(Brow + k0);
        __syncthreads();   // previous iteration's reads complete before overwrite
        As[lk + 0][lr] = av.x; As[lk + 1][lr] = av.y; As[lk + 2][lr] = av.z; As[lk + 3][lr] = av.w;
        Bs[lk + 0][lr] = bv.x; Bs[lk + 1][lr] = bv.y; Bs[lk + 2][lr] = bv.z; Bs[lk + 3][lr] = bv.w;
        __syncthreads();
#pragma unroll
        for (int k = 0; k < 16; k++) {
            float4 a = *(const float4*)&As[k][ty << 2];
            float4 b = *(const float4*)&Bs[k][tx << 2];
            acc[0][0] += a.x * b.x; acc[0][1] += a.x * b.y; acc[0][2] += a.x * b.z; acc[0][3] += a.x * b.w;
            acc[1][0] += a.y * b.x; acc[1][1] += a.y * b.y; acc[1][2] += a.y * b.z; acc[1][3] += a.y * b.w;
            acc[2][0] += a.z * b.x; acc[2][1] += a.z * b.y; acc[2][2] += a.z * b.z; acc[2][3] += a.z * b.w;
            acc[3][0] += a.w * b.x; acc[3][1] += a.w * b.y; acc[3][2] += a.w * b.z; acc[3][3] += a.w * b.w;
        }
    }

#pragma unroll
    for (int r = 0; r < 4; r++) {
        float* C = g_sim + (size_t)(bi + (ty << 2) + r) * n + bj + (tx << 2);
        *(float4*)C = make_float4(acc[r][0], acc[r][1], acc[r][2], acc[r][3]);
    }
}

// ---------------------------------------------------------------------------
// K3: per-row power sums over positives (a = sim/5) and negatives (b = sim/10),
// then the closed-form row loss from the softplus Taylor expansion:
//   softplus(x) = ln2 + x/2 + x^2/8 - x^4/192 + x^6/2880  (|x| <= 0.3 exactly)
//   S = sum_{j in pos, k in neg} softplus(b_k - a_j)
//     expands into products of power sums A_p, B_p.
// One 256-thread block per row.
// ---------------------------------------------------------------------------
__global__ void kreduce(const int* __restrict__ labels, int n) {
    const int i = blockIdx.x;
    const int li = labels[i];
    float A[7], B[7];
#pragma unroll
    for (int p = 0; p < 7; p++) { A[p] = 0.f; B[p] = 0.f; }

    const float* srow = g_sim + (size_t)i * n;
    for (int j = threadIdx.x; j < n; j += blockDim.x) {
        float s = srow[j];
        if (labels[j] == li) {
            if (j != i) {
                float a = s * 0.2f;          // sim / TEMP_POS
                float a2 = a * a, a3 = a2 * a;
                A[0] += 1.f; A[1] += a; A[2] += a2; A[3] += a3;
                A[4] += a2 * a2; A[5] += a2 * a3; A[6] += a3 * a3;
            }
        } else {
            float b = s * 0.1f;              // sim / TEMP_NEG
            float b2 = b * b, b3 = b2 * b;
            B[0] += 1.f; B[1] += b; B[2] += b2; B[3] += b3;
            B[4] += b2 * b2; B[5] += b2 * b3; B[6] += b3 * b3;
        }
    }

    // warp reduce all 14 accumulators
#pragma unroll
    for (int p = 0; p < 7; p++) {
#pragma unroll
        for (int o = 16; o; o >>= 1) {
            A[p] += __shfl_xor_sync(0xffffffffu, A[p], o);
            B[p] += __shfl_xor_sync(0xffffffffu, B[p], o);
        }
    }

    __shared__ float sm[8][14];
    int w = threadIdx.x >> 5, l = threadIdx.x & 31;
    if (l == 0) {
#pragma unroll
        for (int p = 0; p < 7; p++) { sm[w][p] = A[p]; sm[w][7 + p] = B[p]; }
    }
    __syncthreads();

    if (threadIdx.x == 0) {
        for (int k = 1; k < 8; k++) {
#pragma unroll
            for (int p = 0; p < 7; p++) { A[p] += sm[k][p]; B[p] += sm[k][7 + p]; }
        }
        const float LN2 = 0.69314718055994530942f;
        float S = LN2 * A[0] * B[0]
                + 0.5f * (B[1] * A[0] - A[1] * B[0])
                + (1.f / 8.f) * (B[2] * A[0] - 2.f * A[1] * B[1] + A[2] * B[0])
                - (1.f / 192.f) * (B[4] * A[0] - 4.f * B[3] * A[1] + 6.f * B[2] * A[2]
                                   - 4.f * B[1] * A[3] + B[0] * A[4])
                + (1.f / 2880.f) * (B[6] * A[0] - 6.f * B[5] * A[1] + 15.f * B[4] * A[2]
                                    - 20.f * B[3] * A[3] + 15.f * B[2] * A[4]
                                    - 6.f * B[1] * A[5] + B[0] * A[6]);
        float npairs = A[0] * B[0];
        float row_loss = (A[0] > 0.f) ? (S / fmaxf(npairs, 1.f)) : 0.f;
        g_rowloss[i] = row_loss;
        g_rowcnt[i] = (A[0] > 0.f) ? 1.f : 0.f;
    }
}

// ---------------------------------------------------------------------------
// K4: deterministic final reduction over rows.
// ---------------------------------------------------------------------------
__global__ void kfinal(float* __restrict__ out, int n) {
    __shared__ float ss[256], sc[256];
    float s = 0.f, c = 0.f;
    for (int j = threadIdx.x; j < n; j += 256) {
        s += g_rowloss[j];
        c += g_rowcnt[j];
    }
    ss[threadIdx.x] = s; sc[threadIdx.x] = c;
    __syncthreads();
    for (int o = 128; o; o >>= 1) {
        if (threadIdx.x < o) {
            ss[threadIdx.x] += ss[threadIdx.x + o];
            sc[threadIdx.x] += sc[threadIdx.x + o];
        }
        __syncthreads();
    }
    if (threadIdx.x == 0)
        out[0] = (sc[0] > 0.f) ? (ss[0] / fmaxf(sc[0], 1.f)) : 0.f;
}

// ---------------------------------------------------------------------------
extern "C" void kernel_launch(void* const* d_in, const int* in_sizes, int n_in,
                              void* d_out, int out_size) {
    const float* hidden = (const float*)d_in[0];
    const int* labels = (const int*)d_in[1];
    float* out = (float*)d_out;

    int n = in_sizes[1];             // 1024
    int d = in_sizes[0] / n;         // 512

    dim3 nb((n + 7) / 8);
    dim3 nt(32, 8);
    knorm<<<nb, nt>>>(hidden, n, d);

    dim3 gg(n / 64, n / 64);
    kgemm<<<gg, 256>>>(n, d);

    kreduce<<<n, 256>>>(labels, n);

    kfinal<<<1, 256>>>(out, n);
}

// round 2
// speedup vs baseline: 2.1461x; 2.1461x over previous
#include <cuda_runtime.h>
#include <cuda_bf16.h>
#include <cstdint>

// Fixed problem shape: hidden_vectors (1024, 512) f32, labels (1024,) i32.
#define N 1024
#define D 512
#define CB 8        // column blocks of 128 -> grid.x
#define ASTR 40     // smem row stride in bf16 (pad to kill bank conflicts)

__device__ __nv_bfloat16 g_hb[N * D];          // normalized rows, bf16
__device__ float g_partial[14 * CB * N];       // [p][cb][row] power-sum partials

// ---------------------------------------------------------------------------
// K1: L2-normalize rows, emit bf16. One warp per row, blockDim = (32, 8).
// ---------------------------------------------------------------------------
__global__ void knorm(const float* __restrict__ x) {
    int row = blockIdx.x * 8 + threadIdx.y;
    const float4* xr = (const float4*)(x + (size_t)row * D);
    float s = 0.f;
#pragma unroll 4
    for (int i = threadIdx.x; i < D / 4; i += 32) {
        float4 v = xr[i];
        s += v.x * v.x + v.y * v.y + v.z * v.z + v.w * v.w;
    }
#pragma unroll
    for (int o = 16; o; o >>= 1) s += __shfl_xor_sync(0xffffffffu, s, o);
    float inv = rsqrtf(s);
    __nv_bfloat162* hr = (__nv_bfloat162*)(g_hb + (size_t)row * D);
#pragma unroll 4
    for (int i = threadIdx.x; i < D / 4; i += 32) {
        float4 v = xr[i];
        hr[2 * i + 0] = __floats2bfloat162_rn(v.x * inv, v.y * inv);
        hr[2 * i + 1] = __floats2bfloat162_rn(v.z * inv, v.w * inv);
    }
}

// ---------------------------------------------------------------------------
// K2: fused bf16 HMMA GEMM (sim tile 64x128) + power-sum epilogue.
// grid (CB=8, N/64=16), 256 threads = 8 warps (2 row-warps x 4 col-warps),
// warp tile 32x32, mma.sync m16n8k16 bf16 -> f32.
// Never materializes sim: folds tile into per-row power sums
//   A_p = sum_{j pos} (sim/5)^p,  B_p = sum_{k neg} (sim/10)^p,  p = 0..6
// writes deterministic partials g_partial[p][cb][row].
// ---------------------------------------------------------------------------
#define RED4(x) { x += __shfl_xor_sync(0xffffffffu, x, 1); \
                  x += __shfl_xor_sync(0xffffffffu, x, 2); }

__global__ void __launch_bounds__(256, 1) kgemm(const int* __restrict__ labels) {
    __shared__ __align__(16) __nv_bfloat16 As[64 * ASTR];
    __shared__ __align__(16) __nv_bfloat16 Bs[128 * ASTR];
    __shared__ float part[4][64][14];
    __shared__ int lbli[64];
    __shared__ int lblj[128];

    const int bi = blockIdx.y * 64;    // row base
    const int bj = blockIdx.x * 128;   // col base
    const int tid = threadIdx.x;
    const int wid = tid >> 5, lane = tid & 31;
    const int wm = wid & 1;            // row half (0..1)
    const int wn = wid >> 1;           // col quarter (0..3)

    if (tid < 64) lbli[tid] = labels[bi + tid];
    if (tid < 128) lblj[tid] = labels[bj + tid];

    float acc[2][4][4];
#pragma unroll
    for (int mt = 0; mt < 2; mt++)
#pragma unroll
        for (int nt = 0; nt < 4; nt++)
#pragma unroll
            for (int q = 0; q < 4; q++) acc[mt][nt][q] = 0.f;

    const int ar = tid >> 2;           // 0..63
    const int seg = (tid & 3) * 8;     // bf16 offset 0,8,16,24

    for (int k0 = 0; k0 < D; k0 += 32) {
        uint4 av  = *(const uint4*)(g_hb + (size_t)(bi + ar) * D + k0 + seg);
        uint4 bv0 = *(const uint4*)(g_hb + (size_t)(bj + ar) * D + k0 + seg);
        uint4 bv1 = *(const uint4*)(g_hb + (size_t)(bj + 64 + ar) * D + k0 + seg);
        __syncthreads();
        *(uint4*)(As + ar * ASTR + seg) = av;
        *(uint4*)(Bs + ar * ASTR + seg) = bv0;
        *(uint4*)(Bs + (64 + ar) * ASTR + seg) = bv1;
        __syncthreads();

#pragma unroll
        for (int ks = 0; ks < 2; ks++) {
            const int kk = ks * 16 + (lane & 3) * 2;
            uint32_t a[2][4];
#pragma unroll
            for (int mt = 0; mt < 2; mt++) {
                const __nv_bfloat16* base = As + (wm * 32 + mt * 16 + (lane >> 2)) * ASTR;
                a[mt][0] = *(const uint32_t*)(base + kk);
                a[mt][1] = *(const uint32_t*)(base + 8 * ASTR + kk);
                a[mt][2] = *(const uint32_t*)(base + kk + 8);
                a[mt][3] = *(const uint32_t*)(base + 8 * ASTR + kk + 8);
            }
            uint32_t b[4][2];
#pragma unroll
            for (int nt = 0; nt < 4; nt++) {
                const __nv_bfloat16* base = Bs + (wn * 32 + nt * 8 + (lane >> 2)) * ASTR;
                b[nt][0] = *(const uint32_t*)(base + kk);
                b[nt][1] = *(const uint32_t*)(base + kk + 8);
            }
#pragma unroll
            for (int mt = 0; mt < 2; mt++)
#pragma unroll
                for (int nt = 0; nt < 4; nt++) {
                    asm volatile(
                        "mma.sync.aligned.m16n8k16.row.col.f32.bf16.bf16.f32 "
                        "{%0,%1,%2,%3},{%4,%5,%6,%7},{%8,%9},{%0,%1,%2,%3};"
                        : "+f"(acc[mt][nt][0]), "+f"(acc[mt][nt][1]),
                          "+f"(acc[mt][nt][2]), "+f"(acc[mt][nt][3])
                        : "r"(a[mt][0]), "r"(a[mt][1]), "r"(a[mt][2]), "r"(a[mt][3]),
                          "r"(b[nt][0]), "r"(b[nt][1]));
                }
        }
    }

    // ---- epilogue: fold acc tile into per-row power sums ----
#pragma unroll
    for (int mt = 0; mt < 2; mt++)
#pragma unroll
        for (int hf = 0; hf < 2; hf++) {
            const int lr = wm * 32 + mt * 16 + hf * 8 + (lane >> 2);
            const int gr = bi + lr;
            const int li = lbli[lr];
            float A0 = 0, A1 = 0, A2 = 0, A3 = 0, A4 = 0, A5 = 0, A6 = 0;
            float B0 = 0, B1 = 0, B2 = 0, B3 = 0, B4 = 0, B5 = 0, B6 = 0;
#pragma unroll
            for (int nt = 0; nt < 4; nt++)
#pragma unroll
                for (int cc = 0; cc < 2; cc++) {
                    const int lc = wn * 32 + nt * 8 + (lane & 3) * 2 + cc;
                    const float s = acc[mt][nt][hf * 2 + cc];
                    if (bj + lc != gr) {
                        if (lblj[lc] == li) {
                            float a = s * 0.2f;      // sim / TEMP_POS
                            float a2 = a * a, a3 = a2 * a;
                            A0 += 1.f; A1 += a; A2 += a2; A3 += a3;
                            A4 += a2 * a2; A5 += a2 * a3; A6 += a3 * a3;
                        } else {
                            float b = s * 0.1f;      // sim / TEMP_NEG
                            float b2 = b * b, b3 = b2 * b;
                            B0 += 1.f; B1 += b; B2 += b2; B3 += b3;
                            B4 += b2 * b2; B5 += b2 * b3; B6 += b3 * b3;
                        }
                    }
                }
            RED4(A0) RED4(A1) RED4(A2) RED4(A3) RED4(A4) RED4(A5) RED4(A6)
            RED4(B0) RED4(B1) RED4(B2) RED4(B3) RED4(B4) RED4(B5) RED4(B6)
            if ((lane & 3) == 0) {
                float* d = &part[wn][lr][0];
                d[0] = A0; d[1] = A1; d[2] = A2; d[3] = A3; d[4] = A4; d[5] = A5; d[6] = A6;
                d[7] = B0; d[8] = B1; d[9] = B2; d[10] = B3; d[11] = B4; d[12] = B5; d[13] = B6;
            }
        }
    __syncthreads();

    // combine 4 column-warp partials, write coalesced [p][cb][row]
    for (int e = tid; e < 14 * 64; e += 256) {
        const int p = e >> 6, lr = e & 63;
        float s = part[0][lr][p] + part[1][lr][p] + part[2][lr][p] + part[3][lr][p];
        g_partial[p * (CB * N) + blockIdx.x * N + (bi + lr)] = s;
    }
}

// ---------------------------------------------------------------------------
// K3: single block of 1024 threads. Thread r reduces its row's partials over
// the 8 column blocks, applies the closed-form softplus-Taylor row loss:
//   softplus(x) = ln2 + x/2 + x^2/8 - x^4/192 + x^6/2880   (|x| <= 0.3 exact)
// expanded binomially over per-row power sums, then block-reduces to out[0].
// ---------------------------------------------------------------------------
__global__ void __launch_bounds__(1024) kloss(float* __restrict__ out) {
    const int r = threadIdx.x;
    float S[14];
#pragma unroll
    for (int p = 0; p < 14; p++) {
        float s = 0.f;
#pragma unroll
        for (int cb = 0; cb < CB; cb++) s += g_partial[p * (CB * N) + cb * N + r];
        S[p] = s;
    }
    const float A0 = S[0], A1 = S[1], A2 = S[2], A3 = S[3], A4 = S[4], A5 = S[5], A6 = S[6];
    const float B0 = S[7], B1 = S[8], B2 = S[9], B3 = S[10], B4 = S[11], B5 = S[12], B6 = S[13];

    const float LN2 = 0.69314718055994530942f;
    float T = LN2 * A0 * B0
            + 0.5f * (B1 * A0 - A1 * B0)
            + (1.f / 8.f) * (B2 * A0 - 2.f * A1 * B1 + A2 * B0)
            - (1.f / 192.f) * (B4 * A0 - 4.f * B3 * A1 + 6.f * B2 * A2
                               - 4.f * B1 * A3 + B0 * A4)
            + (1.f / 2880.f) * (B6 * A0 - 6.f * B5 * A1 + 15.f * B4 * A2
                                - 20.f * B3 * A3 + 15.f * B2 * A4
                                - 6.f * B1 * A5 + B0 * A6);
    float npairs = A0 * B0;
    float row_loss = (A0 > 0.f) ? (T / fmaxf(npairs, 1.f)) : 0.f;
    float cnt = (A0 > 0.f) ? 1.f : 0.f;

    __shared__ float ss[1024];
    __shared__ float sc[1024];
    ss[r] = row_loss; sc[r] = cnt;
    __syncthreads();
    for (int o = 512; o; o >>= 1) {
        if (r < o) { ss[r] += ss[r + o]; sc[r] += sc[r + o]; }
        __syncthreads();
    }
    if (r == 0)
        out[0] = (sc[0] > 0.f) ? (ss[0] / fmaxf(sc[0], 1.f)) : 0.f;
}

// ---------------------------------------------------------------------------
extern "C" void kernel_launch(void* const* d_in, const int* in_sizes, int n_in,
                              void* d_out, int out_size) {
    const float* hidden = (const float*)d_in[0];
    const int* labels = (const int*)d_in[1];
    float* out = (float*)d_out;

    knorm<<<N / 8, dim3(32, 8)>>>(hidden);
    kgemm<<<dim3(CB, N / 64), 256>>>(labels);
    kloss<<<1, 1024>>>(out);
}

// round 3
// speedup vs baseline: 2.7029x; 1.2594x over previous
#include <cuda_runtime.h>
#include <cuda_bf16.h>
#include <cstdint>

// Fixed shape: hidden_vectors (1024, 512) f32, labels (1024,) i32.
#define N 1024
#define D 512
#define CB 8            // column blocks of 128
#define RB 16           // row blocks of 64
#define GRID (CB * RB)  // 128
#define ASTR 40         // smem row stride (bf16 elems); 80B rows, 16B aligned, conflict-free
#define NP 10           // power sums: A0..A4, B0..B4 (softplus Taylor through x^4)

__device__ float g_partial[NP * CB * N];   // [p][cb][row]
__device__ unsigned g_ctr = 0;

__device__ __forceinline__ float sq4(float4 v) {
    return v.x * v.x + v.y * v.y + v.z * v.z + v.w * v.w;
}
__device__ __forceinline__ void st8(__nv_bfloat16* p, float4 v0, float4 v1) {
    __nv_bfloat162 t[4];
    t[0] = __floats2bfloat162_rn(v0.x, v0.y);
    t[1] = __floats2bfloat162_rn(v0.z, v0.w);
    t[2] = __floats2bfloat162_rn(v1.x, v1.y);
    t[3] = __floats2bfloat162_rn(v1.z, v1.w);
    *(uint4*)p = *(uint4*)t;
}

#define RED4(x) { x += __shfl_xor_sync(0xffffffffu, x, 1); \
                  x += __shfl_xor_sync(0xffffffffu, x, 2); }

// ---------------------------------------------------------------------------
// Single fused kernel:
//   - loads raw f32 x tiles, accumulates per-row sum-of-squares on the fly
//     (invnorm folded into the epilogue: sim = bf16dot * inv_i * inv_j)
//   - double-buffered smem, mma.sync m16n8k16 bf16->f32, 64x128 sim tile
//   - epilogue folds tile into per-row power sums A_p (pos, sim/5) and
//     B_p (neg, sim/10), p=0..4
//   - last-block-done (threadfence + atomic counter, deterministic) reduces
//     partials with the closed-form softplus Taylor:
//       softplus(x) = ln2 + x/2 + x^2/8 - x^4/192   (|x| <= 0.3, err < 4e-7)
// ---------------------------------------------------------------------------
__global__ void __launch_bounds__(256, 1) kfused(const float* __restrict__ x,
                                                 const int* __restrict__ labels,
                                                 float* __restrict__ out) {
    __shared__ __align__(16) __nv_bfloat16 As[2][64 * ASTR];
    __shared__ __align__(16) __nv_bfloat16 Bs[2][128 * ASTR];
    __shared__ float invA[64];
    __shared__ float invB[128];
    __shared__ int lbli[64];
    __shared__ int lblj[128];
    __shared__ float part[4][64][NP];
    __shared__ float fs[256], fc[256];
    __shared__ int isLast;

    const int tid = threadIdx.x;
    const int wid = tid >> 5, lane = tid & 31;
    const int wm = wid & 1;            // row half of warp grid
    const int wn = wid >> 1;           // col quarter
    const int cb = blockIdx.x & (CB - 1);
    const int rb = blockIdx.x >> 3;
    const int bi = rb * 64, bj = cb * 128;

    if (tid < 64) lbli[tid] = labels[bi + tid];
    if (tid < 128) lblj[tid] = labels[bj + tid];

    const int ar = tid >> 2;           // 0..63
    const int seg = (tid & 3) * 8;     // 0,8,16,24

    const float* Ap = x + (size_t)(bi + ar) * D + seg;
    const float* B0p = x + (size_t)(bj + ar) * D + seg;
    const float* B1p = x + (size_t)(bj + 64 + ar) * D + seg;

    float ssA = 0.f, ssB0 = 0.f, ssB1 = 0.f;
    float acc[2][4][4];
#pragma unroll
    for (int mt = 0; mt < 2; mt++)
#pragma unroll
        for (int nt = 0; nt < 4; nt++)
#pragma unroll
            for (int q = 0; q < 4; q++) acc[mt][nt][q] = 0.f;

    // preload chunk 0
    float4 a0 = *(const float4*)(Ap),      a1 = *(const float4*)(Ap + 4);
    float4 b00 = *(const float4*)(B0p),    b01 = *(const float4*)(B0p + 4);
    float4 b10 = *(const float4*)(B1p),    b11 = *(const float4*)(B1p + 4);
    ssA += sq4(a0) + sq4(a1); ssB0 += sq4(b00) + sq4(b01); ssB1 += sq4(b10) + sq4(b11);
    st8(&As[0][ar * ASTR + seg], a0, a1);
    st8(&Bs[0][ar * ASTR + seg], b00, b01);
    st8(&Bs[0][(64 + ar) * ASTR + seg], b10, b11);
    __syncthreads();

#pragma unroll 1
    for (int i = 0; i < 16; i++) {
        const int cur = i & 1;
        if (i < 15) {
            const int off = (i + 1) * 32;
            a0 = *(const float4*)(Ap + off);   a1 = *(const float4*)(Ap + off + 4);
            b00 = *(const float4*)(B0p + off); b01 = *(const float4*)(B0p + off + 4);
            b10 = *(const float4*)(B1p + off); b11 = *(const float4*)(B1p + off + 4);
        }
#pragma unroll
        for (int ks = 0; ks < 2; ks++) {
            const int kk = ks * 16 + (lane & 3) * 2;
            uint32_t a[2][4];
#pragma unroll
            for (int mt = 0; mt < 2; mt++) {
                const __nv_bfloat16* base = &As[cur][(wm * 32 + mt * 16 + (lane >> 2)) * ASTR];
                a[mt][0] = *(const uint32_t*)(base + kk);
                a[mt][1] = *(const uint32_t*)(base + 8 * ASTR + kk);
                a[mt][2] = *(const uint32_t*)(base + kk + 8);
                a[mt][3] = *(const uint32_t*)(base + 8 * ASTR + kk + 8);
            }
            uint32_t b[4][2];
#pragma unroll
            for (int nt = 0; nt < 4; nt++) {
                const __nv_bfloat16* base = &Bs[cur][(wn * 32 + nt * 8 + (lane >> 2)) * ASTR];
                b[nt][0] = *(const uint32_t*)(base + kk);
                b[nt][1] = *(const uint32_t*)(base + kk + 8);
            }
#pragma unroll
            for (int mt = 0; mt < 2; mt++)
#pragma unroll
                for (int nt = 0; nt < 4; nt++) {
                    asm volatile(
                        "mma.sync.aligned.m16n8k16.row.col.f32.bf16.bf16.f32 "
                        "{%0,%1,%2,%3},{%4,%5,%6,%7},{%8,%9},{%0,%1,%2,%3};"
                        : "+f"(acc[mt][nt][0]), "+f"(acc[mt][nt][1]),
                          "+f"(acc[mt][nt][2]), "+f"(acc[mt][nt][3])
                        : "r"(a[mt][0]), "r"(a[mt][1]), "r"(a[mt][2]), "r"(a[mt][3]),
                          "r"(b[nt][0]), "r"(b[nt][1]));
                }
        }
        if (i < 15) {
            ssA += sq4(a0) + sq4(a1); ssB0 += sq4(b00) + sq4(b01); ssB1 += sq4(b10) + sq4(b11);
            const int nxt = cur ^ 1;
            st8(&As[nxt][ar * ASTR + seg], a0, a1);
            st8(&Bs[nxt][ar * ASTR + seg], b00, b01);
            st8(&Bs[nxt][(64 + ar) * ASTR + seg], b10, b11);
            __syncthreads();
        }
    }

    // per-row inverse norms (reduce across the 4 threads sharing a row)
    RED4(ssA) RED4(ssB0) RED4(ssB1)
    if ((tid & 3) == 0) {
        invA[ar] = rsqrtf(ssA);
        invB[ar] = rsqrtf(ssB0);
        invB[64 + ar] = rsqrtf(ssB1);
    }
    __syncthreads();

    // ---- epilogue: power sums ----
#pragma unroll
    for (int mt = 0; mt < 2; mt++)
#pragma unroll
        for (int hf = 0; hf < 2; hf++) {
            const int lr = wm * 32 + mt * 16 + hf * 8 + (lane >> 2);
            const int gr = bi + lr;
            const int li = lbli[lr];
            const float ia = invA[lr];
            float A0 = 0, A1 = 0, A2 = 0, A3 = 0, A4 = 0;
            float B0 = 0, B1 = 0, B2 = 0, B3 = 0, B4 = 0;
#pragma unroll
            for (int nt = 0; nt < 4; nt++)
#pragma unroll
                for (int cc = 0; cc < 2; cc++) {
                    const int lc = wn * 32 + nt * 8 + (lane & 3) * 2 + cc;
                    const float s = acc[mt][nt][hf * 2 + cc] * ia * invB[lc];
                    if (bj + lc != gr) {
                        if (lblj[lc] == li) {
                            float a = s * 0.2f;          // sim / TEMP_POS
                            float a2 = a * a;
                            A0 += 1.f; A1 += a; A2 += a2; A3 += a2 * a; A4 += a2 * a2;
                        } else {
                            float b = s * 0.1f;          // sim / TEMP_NEG
                            float b2 = b * b;
                            B0 += 1.f; B1 += b; B2 += b2; B3 += b2 * b; B4 += b2 * b2;
                        }
                    }
                }
            RED4(A0) RED4(A1) RED4(A2) RED4(A3) RED4(A4)
            RED4(B0) RED4(B1) RED4(B2) RED4(B3) RED4(B4)
            if ((lane & 3) == 0) {
                float* d = &part[wn][lr][0];
                d[0] = A0; d[1] = A1; d[2] = A2; d[3] = A3; d[4] = A4;
                d[5] = B0; d[6] = B1; d[7] = B2; d[8] = B3; d[9] = B4;
            }
        }
    __syncthreads();

    // combine the 4 column-warp partials, coalesced write [p][cb][row]
    for (int e = tid; e < NP * 64; e += 256) {
        const int p = e >> 6, lr = e & 63;
        float s = part[0][lr][p] + part[1][lr][p] + part[2][lr][p] + part[3][lr][p];
        g_partial[p * (CB * N) + cb * N + (bi + lr)] = s;
    }
    __syncthreads();
    __threadfence();

    // last-block-done election (deterministic; counter monotonic across graph replays)
    if (tid == 0) {
        unsigned old = atomicAdd(&g_ctr, 1u);
        isLast = (((old + 1) & (GRID - 1)) == 0) ? 1 : 0;
    }
    __syncthreads();
    if (!isLast) return;
    __threadfence();

    // ---- final reduction (one block, fixed order -> deterministic) ----
    float ls = 0.f, lc = 0.f;
    for (int r = tid; r < N; r += 256) {
        float S[NP];
#pragma unroll
        for (int p = 0; p < NP; p++) {
            float s = 0.f;
#pragma unroll
            for (int c = 0; c < CB; c++) s += g_partial[p * (CB * N) + c * N + r];
            S[p] = s;
        }
        const float A0 = S[0], A1 = S[1], A2 = S[2], A3 = S[3], A4 = S[4];
        const float B0 = S[5], B1 = S[6], B2 = S[7], B3 = S[8], B4 = S[9];
        const float LN2 = 0.69314718055994530942f;
        float T = LN2 * A0 * B0
                + 0.5f * (B1 * A0 - A1 * B0)
                + 0.125f * (B2 * A0 - 2.f * A1 * B1 + A2 * B0)
                - (1.f / 192.f) * (B4 * A0 - 4.f * B3 * A1 + 6.f * B2 * A2
                                   - 4.f * B1 * A3 + B0 * A4);
        float npairs = A0 * B0;
        ls += (A0 > 0.f) ? (T / fmaxf(npairs, 1.f)) : 0.f;
        lc += (A0 > 0.f) ? 1.f : 0.f;
    }
    fs[tid] = ls; fc[tid] = lc;
    __syncthreads();
    for (int o = 128; o; o >>= 1) {
        if (tid < o) { fs[tid] += fs[tid + o]; fc[tid] += fc[tid + o]; }
        __syncthreads();
    }
    if (tid == 0)
        out[0] = (fc[0] > 0.f) ? (fs[0] / fmaxf(fc[0], 1.f)) : 0.f;
}

// ---------------------------------------------------------------------------
extern "C" void kernel_launch(void* const* d_in, const int* in_sizes, int n_in,
                              void* d_out, int out_size) {
    const float* hidden = (const float*)d_in[0];
    const int* labels = (const int*)d_in[1];
    float* out = (float*)d_out;
    kfused<<<GRID, 256>>>(hidden, labels, out);
}

// round 4
// speedup vs baseline: 2.9867x; 1.1050x over previous
#include <cuda_runtime.h>
#include <cuda_bf16.h>
#include <cstdint>

// Fixed shape: hidden_vectors (1024, 512) f32, labels (1024,) i32.
#define N 1024
#define D 512
#define CB 8            // column blocks of 128
#define RB 16           // row blocks of 64
#define GRID (CB * RB)  // 128
#define ASTR 40         // smem row stride in bf16 (80B): LDSM rows hit distinct banks
#define NP 10           // power sums A0..A4, B0..B4 (softplus Taylor through x^4)

__device__ float g_partial[NP * CB * N];   // [p][cb][row]
__device__ unsigned g_ctr = 0;

__device__ __forceinline__ float sq4(float4 v) {
    return v.x * v.x + v.y * v.y + v.z * v.z + v.w * v.w;
}
__device__ __forceinline__ void st4(__nv_bfloat16* p, float4 v) {
    __nv_bfloat162 t[2];
    t[0] = __floats2bfloat162_rn(v.x, v.y);
    t[1] = __floats2bfloat162_rn(v.z, v.w);
    *(uint2*)p = *(uint2*)t;
}
__device__ __forceinline__ void ldsm4(uint32_t* r, uint32_t addr) {
    asm volatile("ldmatrix.sync.aligned.m8n8.x4.shared.b16 {%0,%1,%2,%3},[%4];"
                 : "=r"(r[0]), "=r"(r[1]), "=r"(r[2]), "=r"(r[3]) : "r"(addr));
}

#define RED4(x) { x += __shfl_xor_sync(0xffffffffu, x, 1); \
                  x += __shfl_xor_sync(0xffffffffu, x, 2); }
#define RED8(x) { x += __shfl_xor_sync(0xffffffffu, x, 1); \
                  x += __shfl_xor_sync(0xffffffffu, x, 2); \
                  x += __shfl_xor_sync(0xffffffffu, x, 4); }

// ---------------------------------------------------------------------------
// One fused kernel, 512 threads (16 warps as 4 row x 4 col), tile 64x128.
//  - raw f32 tiles in, sum-of-squares on the fly (invnorm folded in epilogue)
//  - double-buffered smem, ldmatrix.x4 fragment loads, mma m16n8k16 bf16->f32
//  - epilogue: per-row power sums A_p (pos, sim/5), B_p (neg, sim/10), p=0..4
//  - last-block (threadfence + atomic counter, deterministic order) applies
//      softplus(x) = ln2 + x/2 + x^2/8 - x^4/192   (|x| <= 0.3, err < 4e-7)
// ---------------------------------------------------------------------------
__global__ void __launch_bounds__(512, 1) kfused(const float* __restrict__ x,
                                                 const int* __restrict__ labels,
                                                 float* __restrict__ out) {
    __shared__ __align__(16) __nv_bfloat16 As[2][64 * ASTR];
    __shared__ __align__(16) __nv_bfloat16 Bs[2][128 * ASTR];
    __shared__ float invA[64];
    __shared__ float invB[128];
    __shared__ int lbli[64];
    __shared__ int lblj[128];
    __shared__ float part[4][64][NP];
    __shared__ float fs[512], fc[512];
    __shared__ int isLast;

    const int tid = threadIdx.x;
    const int wid = tid >> 5, lane = tid & 31;
    const int wm = wid & 3;            // row group of 16
    const int wn = wid >> 2;           // col group of 32
    const int wr = wm * 16;
    const int wc = wn * 32;
    const int cb = blockIdx.x & (CB - 1);
    const int rb = blockIdx.x >> 3;
    const int bi = rb * 64, bj = cb * 128;

    if (tid < 64) lbli[tid] = labels[bi + tid];
    else if (tid < 192) lblj[tid - 64] = labels[bj + tid - 64];

    // global load mapping: thread t -> row t>>3 (0..63), seg (t&7)*4 (0..28)
    const int gr8 = tid >> 3;
    const int seg = (tid & 7) * 4;
    const float* Ap = x + (size_t)(bi + gr8) * D + seg;
    const float* B0p = x + (size_t)(bj + gr8) * D + seg;
    const float* B1p = x + (size_t)(bj + 64 + gr8) * D + seg;

    // ldmatrix address bases (per-thread, in bytes)
    const uint32_t sA = (uint32_t)__cvta_generic_to_shared(&As[0][0]);
    const uint32_t sB = (uint32_t)__cvta_generic_to_shared(&Bs[0][0]);
    const int arow = wr + (lane & 7) + ((lane >> 3) & 1) * 8;
    const int akof = (lane >> 4) * 8;
    const uint32_t aBase = sA + (uint32_t)(arow * ASTR + akof) * 2u;
    const uint32_t bBase = sB + (uint32_t)((wc + lane) * ASTR) * 2u;
    const uint32_t aBuf = 64u * ASTR * 2u;
    const uint32_t bBuf = 128u * ASTR * 2u;

    float ssA = 0.f, ssB0 = 0.f, ssB1 = 0.f;
    float acc[4][4];
#pragma unroll
    for (int nt = 0; nt < 4; nt++)
#pragma unroll
        for (int q = 0; q < 4; q++) acc[nt][q] = 0.f;

    // preload chunk 0
    float4 av = *(const float4*)(Ap);
    float4 bv0 = *(const float4*)(B0p);
    float4 bv1 = *(const float4*)(B1p);
    ssA += sq4(av); ssB0 += sq4(bv0); ssB1 += sq4(bv1);
    st4(&As[0][gr8 * ASTR + seg], av);
    st4(&Bs[0][gr8 * ASTR + seg], bv0);
    st4(&Bs[0][(64 + gr8) * ASTR + seg], bv1);
    __syncthreads();

#pragma unroll 1
    for (int i = 0; i < 16; i++) {
        const int cur = i & 1;
        if (i < 15) {
            const int off = (i + 1) * 32;
            av = *(const float4*)(Ap + off);
            bv0 = *(const float4*)(B0p + off);
            bv1 = *(const float4*)(B1p + off);
        }
        const uint32_t aB = aBase + cur * aBuf;
        const uint32_t bB = bBase + cur * bBuf;
#pragma unroll
        for (int ks = 0; ks < 2; ks++) {
            uint32_t a[4], b0[4], b1[4];
            ldsm4(a, aB + ks * 32u);
            ldsm4(b0, bB + ks * 32u);
            ldsm4(b1, bB + ks * 32u + 16u);
#pragma unroll
            for (int nt = 0; nt < 4; nt++) {
                asm volatile(
                    "mma.sync.aligned.m16n8k16.row.col.f32.bf16.bf16.f32 "
                    "{%0,%1,%2,%3},{%4,%5,%6,%7},{%8,%9},{%0,%1,%2,%3};"
                    : "+f"(acc[nt][0]), "+f"(acc[nt][1]),
                      "+f"(acc[nt][2]), "+f"(acc[nt][3])
                    : "r"(a[0]), "r"(a[1]), "r"(a[2]), "r"(a[3]),
                      "r"(b0[nt]), "r"(b1[nt]));
            }
        }
        if (i < 15) {
            ssA += sq4(av); ssB0 += sq4(bv0); ssB1 += sq4(bv1);
            const int nxt = cur ^ 1;
            st4(&As[nxt][gr8 * ASTR + seg], av);
            st4(&Bs[nxt][gr8 * ASTR + seg], bv0);
            st4(&Bs[nxt][(64 + gr8) * ASTR + seg], bv1);
            __syncthreads();
        }
    }

    // per-row inverse norms (8 threads share a row)
    RED8(ssA) RED8(ssB0) RED8(ssB1)
    if ((tid & 7) == 0) {
        invA[gr8] = rsqrtf(ssA);
        invB[gr8] = rsqrtf(ssB0);
        invB[64 + gr8] = rsqrtf(ssB1);
    }
    __syncthreads();

    // ---- epilogue: fold acc tile into power sums ----
#pragma unroll
    for (int hf = 0; hf < 2; hf++) {
        const int lr = wr + hf * 8 + (lane >> 2);
        const int gr = bi + lr;
        const int li = lbli[lr];
        const float ia = invA[lr];
        float A0 = 0, A1 = 0, A2 = 0, A3 = 0, A4 = 0;
        float B0 = 0, B1 = 0, B2 = 0, B3 = 0, B4 = 0;
#pragma unroll
        for (int nt = 0; nt < 4; nt++)
#pragma unroll
            for (int cc = 0; cc < 2; cc++) {
                const int lc = wc + nt * 8 + (lane & 3) * 2 + cc;
                const float s = acc[nt][hf * 2 + cc] * ia * invB[lc];
                if (bj + lc != gr) {
                    if (lblj[lc] == li) {
                        float a = s * 0.2f;          // sim / TEMP_POS
                        float a2 = a * a;
                        A0 += 1.f; A1 += a; A2 += a2; A3 += a2 * a; A4 += a2 * a2;
                    } else {
                        float b = s * 0.1f;          // sim / TEMP_NEG
                        float b2 = b * b;
                        B0 += 1.f; B1 += b; B2 += b2; B3 += b2 * b; B4 += b2 * b2;
                    }
                }
            }
        RED4(A0) RED4(A1) RED4(A2) RED4(A3) RED4(A4)
        RED4(B0) RED4(B1) RED4(B2) RED4(B3) RED4(B4)
        if ((lane & 3) == 0) {
            // 4 row-warps cover disjoint lr; col-warps (wn) accumulate in part
            float* d = &part[wn][lr][0];
            d[0] = A0; d[1] = A1; d[2] = A2; d[3] = A3; d[4] = A4;
            d[5] = B0; d[6] = B1; d[7] = B2; d[8] = B3; d[9] = B4;
        }
    }
    __syncthreads();

    // combine 4 column-warp partials, coalesced write [p][cb][row]
    for (int e = tid; e < NP * 64; e += 512) {
        const int p = e >> 6, lr = e & 63;
        float s = part[0][lr][p] + part[1][lr][p] + part[2][lr][p] + part[3][lr][p];
        g_partial[p * (CB * N) + cb * N + (bi + lr)] = s;
    }
    __syncthreads();
    __threadfence();

    // last-block election (counter monotonic; mod GRID works across graph replays)
    if (tid == 0) {
        unsigned old = atomicAdd(&g_ctr, 1u);
        isLast = (((old + 1) & (GRID - 1)) == 0) ? 1 : 0;
    }
    __syncthreads();
    if (!isLast) return;
    __threadfence();

    // ---- final reduction (one block, fixed order -> deterministic) ----
    float ls = 0.f, lc = 0.f;
    for (int r = tid; r < N; r += 512) {
        float S[NP];
#pragma unroll
        for (int p = 0; p < NP; p++) {
            float s = 0.f;
#pragma unroll
            for (int c = 0; c < CB; c++) s += g_partial[p * (CB * N) + c * N + r];
            S[p] = s;
        }
        const float A0 = S[0], A1 = S[1], A2 = S[2], A3 = S[3], A4 = S[4];
        const float B0 = S[5], B1 = S[6], B2 = S[7], B3 = S[8], B4 = S[9];
        const float LN2 = 0.69314718055994530942f;
        float T = LN2 * A0 * B0
                + 0.5f * (B1 * A0 - A1 * B0)
                + 0.125f * (B2 * A0 - 2.f * A1 * B1 + A2 * B0)
                - (1.f / 192.f) * (B4 * A0 - 4.f * B3 * A1 + 6.f * B2 * A2
                                   - 4.f * B1 * A3 + B0 * A4);
        float npairs = A0 * B0;
        ls += (A0 > 0.f) ? (T / fmaxf(npairs, 1.f)) : 0.f;
        lc += (A0 > 0.f) ? 1.f : 0.f;
    }
    fs[tid] = ls; fc[tid] = lc;
    __syncthreads();
    for (int o = 256; o; o >>= 1) {
        if (tid < o) { fs[tid] += fs[tid + o]; fc[tid] += fc[tid + o]; }
        __syncthreads();
    }
    if (tid == 0)
        out[0] = (fc[0] > 0.f) ? (fs[0] / fmaxf(fc[0], 1.f)) : 0.f;
}

// ---------------------------------------------------------------------------
extern "C" void kernel_launch(void* const* d_in, const int* in_sizes, int n_in,
                              void* d_out, int out_size) {
    const float* hidden = (const float*)d_in[0];
    const int* labels = (const int*)d_in[1];
    float* out = (float*)d_out;
    kfused<<<GRID, 512>>>(hidden, labels, out);
}